// round 9
// baseline (speedup 1.0000x reference)
#include <cuda_runtime.h>
#include <math.h>

#define B 64
#define C 512
#define HW 1024
#define R 32
#define T1 128
#define NTILE 16       // HW / 64
#define TN 64          // n per tile
#define NSLOT 16       // one pooled partial per tile

// cp.async helpers (Ampere+)
#define CP_ASYNC16(dst_u32, src_ptr) \
    asm volatile("cp.async.cg.shared.global [%0], [%1], 16;" \
                 :: "r"(dst_u32), "l"(src_ptr))
#define CP_COMMIT() asm volatile("cp.async.commit_group;" ::: "memory")
#define CP_WAIT2()  asm volatile("cp.async.wait_group 2;" ::: "memory")

// ---------------- scratch (device globals: no allocation allowed) -------------
__device__ float g_feat[B * R * HW];        // 8 MB   feat_raw = w_eig @ x (no bias)
__device__ float g_poolpart[B * NSLOT * C]; // 2 MB   partial sums for pooled
__device__ float g_covpart[B * 4 * R * R];  // 1 MB   raw Gram partials
__device__ float g_sp[B * HW];              // 256 KB spatial logits (no bias)
__device__ float g_ca[B * C];               // 128 KB channel attention
__device__ float g_att[B * HW];             // 256 KB eigen_att * spatial_att

// ============================================================================
// Pass 1: scalar-FFMA register GEMM, high occupancy. CTA = (b, 64-n tile),
// grid 1024, 128 threads / 4 warps, ~5 CTAs/SM resident (smem ~31 KB).
// Warp owns 8 r; thread owns 2 n -> 16 scalar accumulators.
// x: GMEM -> SMEM via cp.async.cg 16B, 4 stages x 8 channels, 3 in flight.
// Weight window 128 channels (18 KB), reloaded at chunks 16/32/48.
// Per channel per thread: 1 x-LDS.64 + 2 broadcast w-LDS.128 + 16 FFMA.
// Duty (spatial FMA + pooled shfl chain for channel c): warp c&3.
// ============================================================================
__global__ __launch_bounds__(T1, 5) void pass1(const float* __restrict__ x,
                                               const float* __restrict__ w_eig,
                                               const float* __restrict__ w_sp) {
    __shared__ __align__(16) float we_s[128][36];   // 18 KB window
    __shared__ __align__(16) float xs[4][8][TN];    // 8 KB, 4 stages
    __shared__ float wsp_s[512];
    __shared__ float spool[512];
    __shared__ float sps[4][TN];

    int b = blockIdx.x >> 4;
    int tile = blockIdx.x & 15;
    int n0 = tile * TN;
    int tid = threadIdx.x, lane = tid & 31, warp = tid >> 5;
    int r0 = warp << 3;          // 8 r rows per warp
    int ncol = lane << 1;        // 2 n cols per thread

    const float* xg = x + ((size_t)b * C) * HW + n0;
    unsigned int xs_base = (unsigned int)__cvta_generic_to_shared(&xs[0][0][0]);

    // per-thread copy slot: 1 x 16B per chunk (8 ch x 64 n x 4B = 2 KB)
    int cl0 = tid >> 4;              // channel 0..7 within chunk
    int ns0 = (tid & 15) << 2;       // float offset of 16B segment

#define ISSUE_CHUNK(CC)                                                        \
    {                                                                          \
        int st_ = (CC) & 3;                                                    \
        const float* s0_ = xg + (size_t)((CC) * 8 + cl0) * HW + ns0;           \
        unsigned int d0_ = xs_base + (((st_ * 8 + cl0) * TN) + ns0) * 4u;      \
        CP_ASYNC16(d0_, s0_);                                                  \
    }

    // start DRAM traffic first: 3 chunks in flight
    ISSUE_CHUNK(0) CP_COMMIT();
    ISSUE_CHUNK(1) CP_COMMIT();
    ISSUE_CHUNK(2) CP_COMMIT();

    // stage weight window 0 (channels 0..127), transposed to [cc][r]
    for (int idx = tid; idx < 128 * 32; idx += T1) {
        int rr = idx >> 7;
        int cc = idx & 127;
        we_s[cc][rr] = w_eig[rr * C + cc];
    }
    for (int idx = tid; idx < 512; idx += T1) wsp_s[idx] = w_sp[idx];

    float acc[16];   // [r 0..7][n 0..1]
#pragma unroll
    for (int i = 0; i < 16; i++) acc[i] = 0.f;
    float sp0 = 0.f, sp1 = 0.f;

    __syncthreads();   // we_s/wsp_s staged

    for (int chunk = 0; chunk < 64; chunk++) {
        if (chunk > 0 && (chunk & 15) == 0) {
            __syncthreads();                  // all warps done with old window
            int cbase = chunk << 3;
            for (int idx = tid; idx < 128 * 32; idx += T1) {
                int rr = idx >> 7;
                int cc = idx & 127;
                we_s[cc][rr] = w_eig[rr * C + cbase + cc];
            }
        }
        CP_WAIT2();          // this chunk's copy group complete
        __syncthreads();     // copies + any weight reload visible

        int st = chunk & 3;
        int c0 = chunk << 3;
#pragma unroll
        for (int k = 0; k < 8; k++) {
            int c = c0 + k;
            int cl = c & 127;
            float2 xv = *(const float2*)&xs[st][k][ncol];
            if ((c & 3) == warp) {
                float wv = wsp_s[c];
                sp0 = fmaf(wv, xv.x, sp0);
                sp1 = fmaf(wv, xv.y, sp1);
                float t = xv.x + xv.y;
                t += __shfl_xor_sync(0xffffffffu, t, 16);
                t += __shfl_xor_sync(0xffffffffu, t, 8);
                t += __shfl_xor_sync(0xffffffffu, t, 4);
                t += __shfl_xor_sync(0xffffffffu, t, 2);
                t += __shfl_xor_sync(0xffffffffu, t, 1);
                if (lane == 0) spool[c] = t;
            }
            const float4* wrow = (const float4*)&we_s[cl][r0];
            float4 w0 = wrow[0];
            float4 w1 = wrow[1];
            acc[0]  = fmaf(w0.x, xv.x, acc[0]);
            acc[1]  = fmaf(w0.x, xv.y, acc[1]);
            acc[2]  = fmaf(w0.y, xv.x, acc[2]);
            acc[3]  = fmaf(w0.y, xv.y, acc[3]);
            acc[4]  = fmaf(w0.z, xv.x, acc[4]);
            acc[5]  = fmaf(w0.z, xv.y, acc[5]);
            acc[6]  = fmaf(w0.w, xv.x, acc[6]);
            acc[7]  = fmaf(w0.w, xv.y, acc[7]);
            acc[8]  = fmaf(w1.x, xv.x, acc[8]);
            acc[9]  = fmaf(w1.x, xv.y, acc[9]);
            acc[10] = fmaf(w1.y, xv.x, acc[10]);
            acc[11] = fmaf(w1.y, xv.y, acc[11]);
            acc[12] = fmaf(w1.z, xv.x, acc[12]);
            acc[13] = fmaf(w1.z, xv.y, acc[13]);
            acc[14] = fmaf(w1.w, xv.x, acc[14]);
            acc[15] = fmaf(w1.w, xv.y, acc[15]);
        }

        // issue copies for chunk+3 (stage (chunk+3)&3 was fully read at chunk-1)
        if (chunk < 61) ISSUE_CHUNK(chunk + 3)
        CP_COMMIT();   // one commit per iteration keeps group counting aligned
    }
#undef ISSUE_CHUNK

    // store feat (float2 per r, coalesced within warp)
#pragma unroll
    for (int rl = 0; rl < 8; rl++) {
        *(float2*)&g_feat[((size_t)(b * R + r0 + rl)) * HW + n0 + ncol] =
            make_float2(acc[rl * 2 + 0], acc[rl * 2 + 1]);
    }

    // combine per-warp spatial partials (warp w covered channels c&3==w)
    *(float2*)&sps[warp][ncol] = make_float2(sp0, sp1);
    __syncthreads();
    if (tid < TN) {
        float s = (sps[0][tid] + sps[1][tid]) + (sps[2][tid] + sps[3][tid]);
        g_sp[(size_t)b * HW + n0 + tid] = s;
    }
    for (int idx = tid; idx < C; idx += T1)
        g_poolpart[((size_t)(b * NSLOT) + tile) * C + idx] = spool[idx];
}

// ============================================================================
// Pass 2a: raw Gram partials. CTA = (b, n-quarter of 256), 256 threads.
// ============================================================================
__global__ __launch_bounds__(256) void pass2a() {
    __shared__ __align__(16) float fcT[256][36];
    int b = blockIdx.x >> 2;
    int q = blockIdx.x & 3;
    int tid = threadIdx.x;

    for (int idx = tid; idx < R * 256; idx += 256) {
        int r = idx >> 8, n = idx & 255;
        fcT[n][r] = g_feat[((size_t)(b * R + r)) * HW + q * 256 + n];
    }
    __syncthreads();

    int my_r = tid >> 3;
    int s0 = (tid & 7) << 2;
    float g4[4] = {0.f, 0.f, 0.f, 0.f};
#pragma unroll 8
    for (int n = 0; n < 256; n++) {
        float fr = fcT[n][my_r];
        float4 fs = *(const float4*)&fcT[n][s0];
        g4[0] = fmaf(fr, fs.x, g4[0]);
        g4[1] = fmaf(fr, fs.y, g4[1]);
        g4[2] = fmaf(fr, fs.z, g4[2]);
        g4[3] = fmaf(fr, fs.w, g4[3]);
    }
    *(float4*)&g_covpart[((size_t)(b * 4 + q)) * (R * R) + my_r * R + s0] =
        make_float4(g4[0], g4[1], g4[2], g4[3]);
}

// ============================================================================
// Pass 2b: per-batch finish. pooled -> MLP (g_ca) + mu; cov assembly;
// power iteration; att projection + min/max + sigmoids.
// ============================================================================
__global__ __launch_bounds__(256) void pass2b(const float* __restrict__ w_fc1,
                                              const float* __restrict__ b_fc1,
                                              const float* __restrict__ w_fc2,
                                              const float* __restrict__ b_fc2,
                                              const float* __restrict__ w_eig,
                                              const float* __restrict__ b_sp,
                                              const float* __restrict__ v0) {
    __shared__ float s_pool[C];
    __shared__ float s_mu[R];
    __shared__ float s_ca1[R];
    __shared__ float s_cov[R * R];
    __shared__ float s_v[R];
    __shared__ float s_redmin[8], s_redmax[8];
    __shared__ float s_c0, s_amin, s_amax;

    int b = blockIdx.x;
    int tid = threadIdx.x, lane = tid & 31, warp = tid >> 5;

    // 1. pooled = sum of 16 tile partials / HW
    for (int c = tid; c < C; c += 256) {
        float s = 0.f;
#pragma unroll
        for (int k = 0; k < NSLOT; k++) s += g_poolpart[((size_t)b * NSLOT + k) * C + c];
        s_pool[c] = s * (1.0f / HW);
    }
    __syncthreads();

    // 2. ca1 = relu(pooled @ w_fc1^T + b_fc1); mu = w_eig @ pooled
    for (int k = 0; k < 4; k++) {
        int r = warp + k * 8;
        float s1 = 0.f, s2 = 0.f;
        for (int c = lane; c < C; c += 32) {
            float p = s_pool[c];
            s1 = fmaf(p, w_fc1[r * C + c], s1);
            s2 = fmaf(p, w_eig[r * C + c], s2);
        }
        for (int o = 16; o > 0; o >>= 1) {
            s1 += __shfl_xor_sync(0xffffffffu, s1, o);
            s2 += __shfl_xor_sync(0xffffffffu, s2, o);
        }
        if (lane == 0) {
            s_ca1[r] = fmaxf(s1 + b_fc1[r], 0.f);
            s_mu[r] = s2;
        }
    }
    __syncthreads();

    // 3. channel attention: sigmoid(ca1 @ w_fc2^T + b_fc2)
    for (int c = tid; c < C; c += 256) {
        float a = b_fc2[c];
#pragma unroll
        for (int r = 0; r < R; r++) a = fmaf(s_ca1[r], w_fc2[c * R + r], a);
        g_ca[(size_t)b * C + c] = 1.f / (1.f + expf(-a));
    }

    // 4. cov = (sum_q G_q - HW*mu*mu^T)/(HW-1) + 1e-5 I
    for (int e0 = tid * 4; e0 < R * R; e0 += 256 * 4) {
#pragma unroll
        for (int i = 0; i < 4; i++) {
            int e = e0 + i;
            int r = e >> 5, s = e & 31;
            float g = 0.f;
#pragma unroll
            for (int q = 0; q < 4; q++)
                g += g_covpart[((size_t)(b * 4 + q)) * (R * R) + e];
            float v = (g - (float)HW * s_mu[r] * s_mu[s]) * (1.0f / (HW - 1));
            if (r == s) v += 1e-5f;
            s_cov[e] = v;
        }
    }
    __syncthreads();

    // 5. power iteration (warp 0)
    if (warp == 0) {
        float v = v0[b * R + lane];
        float nr = v * v;
        for (int o = 16; o > 0; o >>= 1) nr += __shfl_xor_sync(0xffffffffu, nr, o);
        v = v / sqrtf(nr);
        for (int it = 0; it < 5; it++) {
            float nv = 0.f;
#pragma unroll
            for (int s = 0; s < R; s++)
                nv = fmaf(s_cov[s * R + lane], __shfl_sync(0xffffffffu, v, s), nv);
            float nn = nv * nv;
            for (int o = 16; o > 0; o >>= 1) nn += __shfl_xor_sync(0xffffffffu, nn, o);
            v = nv / (sqrtf(nn) + 1e-10f);
        }
        s_v[lane] = v;
        float c0 = v * s_mu[lane];
        for (int o = 16; o > 0; o >>= 1) c0 += __shfl_xor_sync(0xffffffffu, c0, o);
        if (lane == 0) s_c0 = c0;
    }
    __syncthreads();

    // 6. att[n] = v . feat_raw[:,n] - c0 ; min/max; sigmoids
    float attv[4];
#pragma unroll
    for (int k = 0; k < 4; k++) {
        int n = k * 256 + tid;
        float a = 0.f;
#pragma unroll
        for (int r = 0; r < R; r++)
            a = fmaf(s_v[r], g_feat[((size_t)(b * R + r)) * HW + n], a);
        attv[k] = a - s_c0;
    }
    float mn = attv[0], mx = attv[0];
#pragma unroll
    for (int k = 1; k < 4; k++) { mn = fminf(mn, attv[k]); mx = fmaxf(mx, attv[k]); }
    for (int o = 16; o > 0; o >>= 1) {
        mn = fminf(mn, __shfl_xor_sync(0xffffffffu, mn, o));
        mx = fmaxf(mx, __shfl_xor_sync(0xffffffffu, mx, o));
    }
    if (lane == 0) { s_redmin[warp] = mn; s_redmax[warp] = mx; }
    __syncthreads();
    if (tid == 0) {
        float a = s_redmin[0], m = s_redmax[0];
        for (int w = 1; w < 8; w++) { a = fminf(a, s_redmin[w]); m = fmaxf(m, s_redmax[w]); }
        s_amin = a; s_amax = m;
    }
    __syncthreads();
    float amin = s_amin;
    float denom = (s_amax - amin) + 1e-10f;
    float bspv = b_sp[0];
#pragma unroll
    for (int k = 0; k < 4; k++) {
        int n = k * 256 + tid;
        float e = 1.f / (1.f + expf(-((attv[k] - amin) / denom)));
        float sl = g_sp[(size_t)b * HW + n] + bspv;
        float sa = 1.f / (1.f + expf(-sl));
        g_att[(size_t)b * HW + n] = e * sa;
    }
}

// ============================================================================
// Pass 3: out = x * (1 + ca[b,c] * att[b,n])  (4x float4, streaming hints)
// ============================================================================
__global__ __launch_bounds__(256) void pass3(const float* __restrict__ x,
                                             float* __restrict__ out) {
    unsigned int base = blockIdx.x * 1024u + threadIdx.x;
#pragma unroll
    for (int u = 0; u < 4; u++) {
        unsigned int i = base + u * 256u;      // float4 index
        int n4 = i & 255;                      // HW/4 = 256
        int c = (i >> 8) & (C - 1);
        int b = i >> 17;
        float ca = g_ca[b * C + c];
        float4 at = ((const float4*)g_att)[(size_t)b * (HW / 4) + n4];
        float4 xv = __ldcs(((const float4*)x) + i);
        float4 o;
        o.x = fmaf(xv.x, ca * at.x, xv.x);
        o.y = fmaf(xv.y, ca * at.y, xv.y);
        o.z = fmaf(xv.z, ca * at.z, xv.z);
        o.w = fmaf(xv.w, ca * at.w, xv.w);
        __stcs(((float4*)out) + i, o);
    }
}

extern "C" void kernel_launch(void* const* d_in, const int* in_sizes, int n_in,
                              void* d_out, int out_size) {
    const float* x     = (const float*)d_in[0];
    const float* w_fc1 = (const float*)d_in[1];
    const float* b_fc1 = (const float*)d_in[2];
    const float* w_fc2 = (const float*)d_in[3];
    const float* b_fc2 = (const float*)d_in[4];
    const float* w_eig = (const float*)d_in[5];
    /* d_in[6] = b_eig: cancels in feat_c and in mu -> unused */
    const float* w_sp  = (const float*)d_in[7];
    const float* b_sp  = (const float*)d_in[8];
    const float* v0    = (const float*)d_in[9];
    float* out = (float*)d_out;

    pass1<<<B * NTILE, T1>>>(x, w_eig, w_sp);
    pass2a<<<B * 4, 256>>>();
    pass2b<<<B, 256>>>(w_fc1, b_fc1, w_fc2, b_fc2, w_eig, b_sp, v0);
    pass3<<<(B * C * HW / 4) / 1024, 256>>>(x, out);
}